// round 16
// baseline (speedup 1.0000x reference)
#include <cuda_runtime.h>
#include <cuda_bf16.h>
#include <math.h>
#include <stdint.h>

// out[n][m] = -sqrt(max(||a_n||^2 + ||b_m||^2 - 2 <a_n,b_m>, 0))
// Round 16: bf16 + warp tile 64x64 (16 MAC/B of LDSM traffic).
//  - CTA 128x128, 128 threads (4 warps, 2m x 2n), warp tile 64x64.
//  - Whole K=128 resident (66KB smem) -> 2 CTAs/SM; double-buffered frags.
//  - Pre-pass converts fp32 -> bf16 scratch + fp32 norms.
//  - Epilogue staged through conflict-free smem -> coalesced STG.128.

#define DDIM 128
#define TM   128
#define TN   128

__device__ float g_a2[8192];
__device__ float g_b2[8192];
__device__ __nv_bfloat16 g_Abf[8192 * 128];
__device__ __nv_bfloat16 g_Bbf[8192 * 128];

// One warp per row: fp32 norm + bf16 conversion.
__global__ void prep_kernel(const float* __restrict__ A,
                            const float* __restrict__ B, int N, int M) {
    int row  = blockIdx.x * 8 + (threadIdx.x >> 5);
    int lane = threadIdx.x & 31;
    const float* src;
    float* dst;
    __nv_bfloat16* bdst;
    if (row < N) {
        src = A + (size_t)row * DDIM; dst = g_a2 + row;
        bdst = g_Abf + (size_t)row * DDIM;
    } else {
        int r = row - N;
        if (r >= M) return;
        src = B + (size_t)r * DDIM; dst = g_b2 + r;
        bdst = g_Bbf + (size_t)r * DDIM;
    }
    float4 v = reinterpret_cast<const float4*>(src)[lane];
    __nv_bfloat162 p0 = __float22bfloat162_rn(make_float2(v.x, v.y));
    __nv_bfloat162 p1 = __float22bfloat162_rn(make_float2(v.z, v.w));
    reinterpret_cast<__nv_bfloat162*>(bdst)[lane * 2]     = p0;
    reinterpret_cast<__nv_bfloat162*>(bdst)[lane * 2 + 1] = p1;
    float s = v.x * v.x + v.y * v.y + v.z * v.z + v.w * v.w;
    #pragma unroll
    for (int o = 16; o; o >>= 1) s += __shfl_xor_sync(0xffffffffu, s, o);
    if (lane == 0) *dst = s;
}

__device__ __forceinline__ uint32_t smem_u32(const void* p) {
    uint32_t a;
    asm("{ .reg .u64 t; cvta.to.shared.u64 t, %1; cvt.u32.u64 %0, t; }"
        : "=r"(a) : "l"(p));
    return a;
}
__device__ __forceinline__ void mma_bf16(float* c, const uint32_t* a,
                                         const uint32_t* b) {
    asm volatile(
        "mma.sync.aligned.m16n8k16.row.col.f32.bf16.bf16.f32 "
        "{%0,%1,%2,%3}, {%4,%5,%6,%7}, {%8,%9}, {%0,%1,%2,%3};"
        : "+f"(c[0]), "+f"(c[1]), "+f"(c[2]), "+f"(c[3])
        : "r"(a[0]), "r"(a[1]), "r"(a[2]), "r"(a[3]), "r"(b[0]), "r"(b[1]));
}
__device__ __forceinline__ void ldsm_x4(uint32_t* r, uint32_t addr) {
    asm volatile(
        "ldmatrix.sync.aligned.m8n8.x4.shared.b16 {%0,%1,%2,%3}, [%4];"
        : "=r"(r[0]), "=r"(r[1]), "=r"(r[2]), "=r"(r[3]) : "r"(addr));
}
__device__ __forceinline__ void cp_async16(uint32_t dst, const void* src) {
    asm volatile("cp.async.cg.shared.global [%0], [%1], 16;"
                 :: "r"(dst), "l"(src));
}
#define CP_COMMIT() asm volatile("cp.async.commit_group;" ::: "memory")
#define CP_WAIT0()  asm volatile("cp.async.wait_group 0;" ::: "memory")

// FFMA-only sqrt: magic rsqrt + 2 Newton steps; 0 -> 0 (no NaN).
__device__ __forceinline__ float fast_sqrt(float x) {
    float y = __int_as_float(0x5f3759df - (__float_as_int(x) >> 1));
    float h = 0.5f * x;
    y = y * (1.5f - h * y * y);
    y = y * (1.5f - h * y * y);
    return x * y;
}

// smem (floats): Abf tile 32KB = 8192 | Bbf tile 32KB = 8192 | a2s 128 | b2s 128
// Epilogue staging (4 warps x 16 x 72 = 4608 floats) reuses the tile region.
#define AS_F    0
#define BS_F    8192
#define A2S_F   16384
#define B2S_F   16512
#define SMEM_FLOATS 16640
#define SMEM_BYTES  (SMEM_FLOATS * 4)
#define STG_STRIDE  72

__global__ __launch_bounds__(128, 2)
void dist_mma_kernel(float* __restrict__ out, int N, int M) {
    extern __shared__ float smem[];
    float* a2s = smem + A2S_F;
    float* b2s = smem + B2S_F;

    const int tid  = threadIdx.x;
    const int wid  = tid >> 5;      // 0..3
    const int lane = tid & 31;
    const int g    = lane >> 2;
    const int tig  = lane & 3;
    const int row0 = blockIdx.y * TM;
    const int col0 = blockIdx.x * TN;

    const uint32_t SA  = smem_u32(smem);
    const uint32_t AsA = SA;                 // bf16 A tile base
    const uint32_t BsA = SA + BS_F * 4;      // bf16 B tile base

    a2s[tid] = g_a2[row0 + tid];    // 128 threads cover all 128 rows
    b2s[tid] = g_b2[col0 + tid];

    // ---- cp.async whole tiles: row r (256B), granule t (16B = 8 bf16) ----
    // dst granule swizzle: t' = t ^ (r & 7)
    const __nv_bfloat16* Agb = g_Abf + (size_t)row0 * DDIM;
    const __nv_bfloat16* Bgb = g_Bbf + (size_t)col0 * DDIM;
    #pragma unroll
    for (int i = 0; i < 16; i++) {
        int f = tid + i * 128;          // 0..2047 granules
        int r = f >> 4, t = f & 15;
        uint32_t off = (uint32_t)r * 256 + (uint32_t)((t ^ (r & 7)) << 4);
        cp_async16(AsA + off, Agb + (size_t)r * DDIM + t * 8);
        cp_async16(BsA + off, Bgb + (size_t)r * DDIM + t * 8);
    }
    CP_COMMIT();
    CP_WAIT0();
    __syncthreads();

    // ---- warp tiling: 2(m) x 2(n); warp tile 64x64; k-step = 16 ----
    const int mb = (wid & 1) * 64;
    const int nb = (wid >> 1) * 64;

    // ldmatrix lane mappings (granule-space):
    const int rA_l = lane & 15;
    const int dtA  = lane >> 4;          // granule within k-step (0/1)
    const int rB_l = (lane & 7) + ((lane >> 4) << 3);
    const int dtB  = (lane >> 3) & 1;

    uint32_t aBase[4], bBase[4];
    int aXc[4], bXc[4];
    #pragma unroll
    for (int mt = 0; mt < 4; mt++) {
        int r = mb + mt * 16 + rA_l;
        aBase[mt] = AsA + (uint32_t)r * 256;
        aXc[mt]   = r & 7;
    }
    #pragma unroll
    for (int q = 0; q < 4; q++) {
        int r = nb + q * 16 + rB_l;
        bBase[q] = BsA + (uint32_t)r * 256;
        bXc[q]   = r & 7;
    }

    float acc[4][8][4];
    #pragma unroll
    for (int mt = 0; mt < 4; mt++)
        #pragma unroll
        for (int nt = 0; nt < 8; nt++)
            #pragma unroll
            for (int e = 0; e < 4; e++) acc[mt][nt][e] = 0.0f;

    uint32_t af[2][4][4];   // [buf][mt][reg]
    uint32_t bf[2][8][2];   // [buf][nt][reg]

    #define LOAD_FRAGS(ks, buf)                                               \
        do {                                                                  \
            int tk = (ks) * 2;                                                \
            _Pragma("unroll")                                                 \
            for (int mt = 0; mt < 4; mt++)                                    \
                ldsm_x4(af[buf][mt],                                          \
                        aBase[mt] + (((tk + dtA) ^ aXc[mt]) << 4));           \
            _Pragma("unroll")                                                 \
            for (int q = 0; q < 4; q++) {                                     \
                uint32_t t4[4];                                               \
                ldsm_x4(t4, bBase[q] + (((tk + dtB) ^ bXc[q]) << 4));         \
                bf[buf][q * 2 + 0][0] = t4[0];                                \
                bf[buf][q * 2 + 0][1] = t4[1];                                \
                bf[buf][q * 2 + 1][0] = t4[2];                                \
                bf[buf][q * 2 + 1][1] = t4[3];                                \
            }                                                                 \
        } while (0)

    LOAD_FRAGS(0, 0);
    #pragma unroll
    for (int ks = 0; ks < 8; ks++) {
        int cur = ks & 1;
        if (ks < 7) LOAD_FRAGS(ks + 1, cur ^ 1);
        #pragma unroll
        for (int mt = 0; mt < 4; mt++)
            #pragma unroll
            for (int nt = 0; nt < 8; nt++)
                mma_bf16(acc[mt][nt], af[cur][mt], bf[cur][nt]);
    }
    #undef LOAD_FRAGS

    // ---- epilogue: stage -> conflict-free smem -> coalesced STG.128 ----
    __syncthreads();               // done with tiles; reuse as staging
    float* stg = smem + wid * (16 * STG_STRIDE);

    const int cl   = 4 * (lane & 15);
    const int rsel = lane >> 4;
    const float4 b2v = *reinterpret_cast<const float4*>(&b2s[nb + cl]);
    const int xw = ((g >> 2) & 1) << 2;

    #pragma unroll
    for (int mt = 0; mt < 4; mt++) {
        #pragma unroll
        for (int nt = 0; nt < 8; nt++) {
            int c = (nt * 8 + 2 * tig) ^ xw;
            *reinterpret_cast<float2*>(&stg[g * STG_STRIDE + c]) =
                make_float2(acc[mt][nt][0], acc[mt][nt][1]);
            *reinterpret_cast<float2*>(&stg[(g + 8) * STG_STRIDE + c]) =
                make_float2(acc[mt][nt][2], acc[mt][nt][3]);
        }
        __syncwarp();
        #pragma unroll
        for (int rr = 0; rr < 8; rr++) {
            int r = rr * 2 + rsel;
            int xorv = ((r >> 2) & 1) << 2;
            float4 v = *reinterpret_cast<const float4*>(
                &stg[r * STG_STRIDE + (cl ^ xorv)]);
            float a2r = a2s[mb + mt * 16 + r];
            float4 o;
            o.x = -fast_sqrt(fmaxf(fmaf(-2.0f, v.x, a2r + b2v.x), 0.0f));
            o.y = -fast_sqrt(fmaxf(fmaf(-2.0f, v.y, a2r + b2v.y), 0.0f));
            o.z = -fast_sqrt(fmaxf(fmaf(-2.0f, v.z, a2r + b2v.z), 0.0f));
            o.w = -fast_sqrt(fmaxf(fmaf(-2.0f, v.w, a2r + b2v.w), 0.0f));
            *reinterpret_cast<float4*>(
                &out[(size_t)(row0 + mb + mt * 16 + r) * M + (col0 + nb + cl)])
                = o;
        }
        __syncwarp();
    }
}

extern "C" void kernel_launch(void* const* d_in, const int* in_sizes, int n_in,
                              void* d_out, int out_size) {
    const float* A = (const float*)d_in[0];   // z_anc [N,128]
    const float* B = (const float*)d_in[1];   // z_pos_neg [M,128]
    float* out = (float*)d_out;

    const int N = in_sizes[0] / DDIM;
    const int M = in_sizes[1] / DDIM;

    // First call is the (non-captured) correctness run; capture-safe.
    static bool attr_ok = [] {
        cudaFuncSetAttribute(dist_mma_kernel,
                             cudaFuncAttributeMaxDynamicSharedMemorySize,
                             SMEM_BYTES);
        return true;
    }();
    (void)attr_ok;

    int totalRows = N + M;
    prep_kernel<<<(totalRows + 7) / 8, 256>>>(A, B, N, M);

    dim3 grid(M / TN, N / TM);
    dist_mma_kernel<<<grid, 128, SMEM_BYTES>>>(out, N, M);
}

// round 17
// speedup vs baseline: 1.0691x; 1.0691x over previous
#include <cuda_runtime.h>
#include <cuda_bf16.h>
#include <math.h>
#include <stdint.h>

// out[n][m] = -sqrt(max(||a_n||^2 + ||b_m||^2 - 2 <a_n,b_m>, 0))
// Round 17: round-15 champion config (bf16 m16n8k16, 256 thr, warp tile
// 32x64, 2 CTAs/SM) with ONE change: the FFMA Newton sqrt is replaced by
// a single MUFU sqrt.approx.f32. The Newton chain burned ~40us of the
// contended fma/alu pipes; MUFU is idle and does the same work in ~15us
// fully overlapped (round-1 MUFU-cost estimate was off 32x: element ops
// vs warp-instructions).

#define DDIM 128
#define TM   128
#define TN   128

__device__ float g_a2[8192];
__device__ float g_b2[8192];
__device__ __nv_bfloat16 g_Abf[8192 * 128];
__device__ __nv_bfloat16 g_Bbf[8192 * 128];

// One warp per row: fp32 norm + bf16 conversion.
__global__ void prep_kernel(const float* __restrict__ A,
                            const float* __restrict__ B, int N, int M) {
    int row  = blockIdx.x * 8 + (threadIdx.x >> 5);
    int lane = threadIdx.x & 31;
    const float* src;
    float* dst;
    __nv_bfloat16* bdst;
    if (row < N) {
        src = A + (size_t)row * DDIM; dst = g_a2 + row;
        bdst = g_Abf + (size_t)row * DDIM;
    } else {
        int r = row - N;
        if (r >= M) return;
        src = B + (size_t)r * DDIM; dst = g_b2 + r;
        bdst = g_Bbf + (size_t)r * DDIM;
    }
    float4 v = reinterpret_cast<const float4*>(src)[lane];
    __nv_bfloat162 p0 = __float22bfloat162_rn(make_float2(v.x, v.y));
    __nv_bfloat162 p1 = __float22bfloat162_rn(make_float2(v.z, v.w));
    reinterpret_cast<__nv_bfloat162*>(bdst)[lane * 2]     = p0;
    reinterpret_cast<__nv_bfloat162*>(bdst)[lane * 2 + 1] = p1;
    float s = v.x * v.x + v.y * v.y + v.z * v.z + v.w * v.w;
    #pragma unroll
    for (int o = 16; o; o >>= 1) s += __shfl_xor_sync(0xffffffffu, s, o);
    if (lane == 0) *dst = s;
}

__device__ __forceinline__ uint32_t smem_u32(const void* p) {
    uint32_t a;
    asm("{ .reg .u64 t; cvta.to.shared.u64 t, %1; cvt.u32.u64 %0, t; }"
        : "=r"(a) : "l"(p));
    return a;
}
__device__ __forceinline__ void mma_bf16(float* c, const uint32_t* a,
                                         const uint32_t* b) {
    asm volatile(
        "mma.sync.aligned.m16n8k16.row.col.f32.bf16.bf16.f32 "
        "{%0,%1,%2,%3}, {%4,%5,%6,%7}, {%8,%9}, {%0,%1,%2,%3};"
        : "+f"(c[0]), "+f"(c[1]), "+f"(c[2]), "+f"(c[3])
        : "r"(a[0]), "r"(a[1]), "r"(a[2]), "r"(a[3]), "r"(b[0]), "r"(b[1]));
}
__device__ __forceinline__ void ldsm_x4(uint32_t* r, uint32_t addr) {
    asm volatile(
        "ldmatrix.sync.aligned.m8n8.x4.shared.b16 {%0,%1,%2,%3}, [%4];"
        : "=r"(r[0]), "=r"(r[1]), "=r"(r[2]), "=r"(r[3]) : "r"(addr));
}
__device__ __forceinline__ void cp_async16(uint32_t dst, const void* src) {
    asm volatile("cp.async.cg.shared.global [%0], [%1], 16;"
                 :: "r"(dst), "l"(src));
}
#define CP_COMMIT() asm volatile("cp.async.commit_group;" ::: "memory")
#define CP_WAIT0()  asm volatile("cp.async.wait_group 0;" ::: "memory")

// MUFU sqrt: ~1 ulp, sqrt(0) = 0. Runs on the otherwise-idle MUFU pipe.
__device__ __forceinline__ float approx_sqrt(float x) {
    float r;
    asm("sqrt.approx.f32 %0, %1;" : "=f"(r) : "f"(x));
    return r;
}

// smem (floats): Abf tile 32KB = 8192 | Bbf tile 32KB = 8192 | a2s 128 | b2s 128
// Epilogue staging (8 warps x 16 x 72 = 9216 floats) reuses the tile region.
#define AS_F    0
#define BS_F    8192
#define A2S_F   16384
#define B2S_F   16512
#define SMEM_FLOATS 16640
#define SMEM_BYTES  (SMEM_FLOATS * 4)
#define STG_STRIDE  72

__global__ __launch_bounds__(256, 2)
void dist_mma_kernel(float* __restrict__ out, int N, int M) {
    extern __shared__ float smem[];
    float* a2s = smem + A2S_F;
    float* b2s = smem + B2S_F;

    const int tid  = threadIdx.x;
    const int wid  = tid >> 5;      // 0..7
    const int lane = tid & 31;
    const int g    = lane >> 2;
    const int tig  = lane & 3;
    const int row0 = blockIdx.y * TM;
    const int col0 = blockIdx.x * TN;

    const uint32_t SA = smem_u32(smem);
    const uint32_t AsA = SA;                 // bf16 A tile base
    const uint32_t BsA = SA + BS_F * 4;      // bf16 B tile base

    if (tid < 128)      a2s[tid] = g_a2[row0 + tid];
    else                b2s[tid - 128] = g_b2[col0 + tid - 128];

    // ---- cp.async whole tiles: row r (256B), granule t (16B = 8 bf16) ----
    // dst granule swizzle: t' = t ^ (r & 7)
    const __nv_bfloat16* Agb = g_Abf + (size_t)row0 * DDIM;
    const __nv_bfloat16* Bgb = g_Bbf + (size_t)col0 * DDIM;
    #pragma unroll
    for (int i = 0; i < 8; i++) {
        int f = tid + i * 256;          // 0..2047 granules
        int r = f >> 4, t = f & 15;
        uint32_t off = (uint32_t)r * 256 + (uint32_t)((t ^ (r & 7)) << 4);
        cp_async16(AsA + off, Agb + (size_t)r * DDIM + t * 8);
        cp_async16(BsA + off, Bgb + (size_t)r * DDIM + t * 8);
    }
    CP_COMMIT();
    CP_WAIT0();
    __syncthreads();

    // ---- warp tiling: 4(m) x 2(n); warp tile 32x64; k-step = 16 ----
    const int mb = (wid & 3) * 32;
    const int nb = (wid >> 2) * 64;

    // ldmatrix lane mappings (granule-space):
    const int rA_l = lane & 15;
    const int dtA  = lane >> 4;          // granule within k-step (0/1)
    const int rB_l = (lane & 7) + ((lane >> 4) << 3);
    const int dtB  = (lane >> 3) & 1;

    uint32_t aBase[2], bBase[4];
    int aXc[2], bXc[4];
    #pragma unroll
    for (int mt = 0; mt < 2; mt++) {
        int r = mb + mt * 16 + rA_l;
        aBase[mt] = AsA + (uint32_t)r * 256;
        aXc[mt]   = r & 7;
    }
    #pragma unroll
    for (int q = 0; q < 4; q++) {
        int r = nb + q * 16 + rB_l;
        bBase[q] = BsA + (uint32_t)r * 256;
        bXc[q]   = r & 7;
    }

    float acc[2][8][4];
    #pragma unroll
    for (int mt = 0; mt < 2; mt++)
        #pragma unroll
        for (int nt = 0; nt < 8; nt++)
            #pragma unroll
            for (int e = 0; e < 4; e++) acc[mt][nt][e] = 0.0f;

    uint32_t af[2][4];
    uint32_t bf[8][2];

    #pragma unroll
    for (int ks = 0; ks < 8; ks++) {
        int tk = ks * 2;
        #pragma unroll
        for (int mt = 0; mt < 2; mt++)
            ldsm_x4(af[mt], aBase[mt] + (((tk + dtA) ^ aXc[mt]) << 4));
        #pragma unroll
        for (int q = 0; q < 4; q++) {
            uint32_t t4[4];
            ldsm_x4(t4, bBase[q] + (((tk + dtB) ^ bXc[q]) << 4));
            bf[q * 2 + 0][0] = t4[0];
            bf[q * 2 + 0][1] = t4[1];
            bf[q * 2 + 1][0] = t4[2];
            bf[q * 2 + 1][1] = t4[3];
        }
        #pragma unroll
        for (int mt = 0; mt < 2; mt++)
            #pragma unroll
            for (int nt = 0; nt < 8; nt++)
                mma_bf16(acc[mt][nt], af[mt], bf[nt]);
    }

    // ---- epilogue: stage -> conflict-free smem -> coalesced STG.128 ----
    __syncthreads();               // done with tiles; reuse as staging
    float* stg = smem + wid * (16 * STG_STRIDE);

    const int cl   = 4 * (lane & 15);
    const int rsel = lane >> 4;
    const float4 b2v = *reinterpret_cast<const float4*>(&b2s[nb + cl]);
    const int xw = ((g >> 2) & 1) << 2;

    #pragma unroll
    for (int mt = 0; mt < 2; mt++) {
        #pragma unroll
        for (int nt = 0; nt < 8; nt++) {
            int c = (nt * 8 + 2 * tig) ^ xw;
            *reinterpret_cast<float2*>(&stg[g * STG_STRIDE + c]) =
                make_float2(acc[mt][nt][0], acc[mt][nt][1]);
            *reinterpret_cast<float2*>(&stg[(g + 8) * STG_STRIDE + c]) =
                make_float2(acc[mt][nt][2], acc[mt][nt][3]);
        }
        __syncwarp();
        #pragma unroll
        for (int rr = 0; rr < 8; rr++) {
            int r = rr * 2 + rsel;
            int xorv = ((r >> 2) & 1) << 2;
            float4 v = *reinterpret_cast<const float4*>(
                &stg[r * STG_STRIDE + (cl ^ xorv)]);
            float a2r = a2s[mb + mt * 16 + r];
            float4 o;
            o.x = -approx_sqrt(fmaxf(fmaf(-2.0f, v.x, a2r + b2v.x), 0.0f));
            o.y = -approx_sqrt(fmaxf(fmaf(-2.0f, v.y, a2r + b2v.y), 0.0f));
            o.z = -approx_sqrt(fmaxf(fmaf(-2.0f, v.z, a2r + b2v.z), 0.0f));
            o.w = -approx_sqrt(fmaxf(fmaf(-2.0f, v.w, a2r + b2v.w), 0.0f));
            *reinterpret_cast<float4*>(
                &out[(size_t)(row0 + mb + mt * 16 + r) * M + (col0 + nb + cl)])
                = o;
        }
        __syncwarp();
    }
}

extern "C" void kernel_launch(void* const* d_in, const int* in_sizes, int n_in,
                              void* d_out, int out_size) {
    const float* A = (const float*)d_in[0];   // z_anc [N,128]
    const float* B = (const float*)d_in[1];   // z_pos_neg [M,128]
    float* out = (float*)d_out;

    const int N = in_sizes[0] / DDIM;
    const int M = in_sizes[1] / DDIM;

    // First call is the (non-captured) correctness run; capture-safe.
    static bool attr_ok = [] {
        cudaFuncSetAttribute(dist_mma_kernel,
                             cudaFuncAttributeMaxDynamicSharedMemorySize,
                             SMEM_BYTES);
        return true;
    }();
    (void)attr_ok;

    int totalRows = N + M;
    prep_kernel<<<(totalRows + 7) / 8, 256>>>(A, B, N, M);

    dim3 grid(M / TN, N / TM);
    dist_mma_kernel<<<grid, 256, SMEM_BYTES>>>(out, N, M);
}